// round 11
// baseline (speedup 1.0000x reference)
#include <cuda_runtime.h>
#include <cuda_fp16.h>
#include <cstdint>

// ---------------- problem constants ----------------
#define NTOK   131072
#define RAWOB  120
#define NTP    5
#define NEXP   10
#define DDIM   126
#define HDIM   128
#define NACT   16
#define TILE_M 128
#define NPAD   (NTOK + NEXP * TILE_M) // 132352
#define NTILES (NPAD / TILE_M)        // 1034
#define NHBLK  512                    // histogram blocks

// dynamic smem: three 128x128 fp16 tiles (32KB each)
#define A_OFF   0
#define BH_OFF  32768
#define BL_OFF  65536
#define DYN_SMEM 98304

// ---------------- scratch ----------------
__device__ int g_counts[NEXP];
__device__ int g_cursor[NEXP];
__device__ int g_pbase[NEXP + 1];
__device__ int g_sidx[NPAD];
__device__ int g_part[NEXP][NHBLK];
__device__ unsigned int g_tick = 0;   // self-resetting ticket

// pre-swizzled fp16 hi/lo weight tiles; slot NEXP = critic Wc1
__device__ uint4 g_w1h[(NEXP + 1) * 2048];  // 32KB per net
__device__ uint4 g_w1l[(NEXP + 1) * 2048];
__device__ uint4 g_w2h[NEXP * 256];         // 4KB per expert (16x128)
__device__ uint4 g_w2l[NEXP * 256];

// tile element byte offset: 256B rows, 16B chunks XOR-swizzled by row
__device__ __forceinline__ uint32_t toff(int row, int k) {
    return (uint32_t)(row * 256 + (((k >> 3) ^ (row & 7)) << 4) + (k & 7) * 2);
}
__device__ __forceinline__ void cvt_hilo(float a, float b, uint32_t& hi, uint32_t& lo) {
    __half2 h2 = __floats2half2_rn(a, b);
    float2 bk = __half22float2(h2);
    __half2 l2 = __floats2half2_rn(a - bk.x, b - bk.y);
    hi = reinterpret_cast<uint32_t&>(h2);
    lo = reinterpret_cast<uint32_t&>(l2);
}
__device__ __forceinline__ uint32_t cvt_h2(float a, float b) {
    __half2 h2 = __floats2half2_rn(a, b);
    return reinterpret_cast<uint32_t&>(h2);
}

// ---------------- hist (partials) + scan (ticket) ----------------
__global__ void k_histscan(const int* __restrict__ pick) {
    __shared__ int h[NEXP];
    __shared__ int s_last;
    __shared__ int s_cnt[NEXP];
    int tid = threadIdx.x;
    if (tid < NEXP) h[tid] = 0;
    __syncthreads();
    int n = blockIdx.x * blockDim.x + tid;
    if (n < NTOK) atomicAdd(&h[pick[n]], 1);
    __syncthreads();
    if (tid < NEXP) g_part[tid][blockIdx.x] = h[tid];
    __threadfence();
    __syncthreads();
    if (tid == 0)
        s_last = (atomicAdd(&g_tick, 1u) == gridDim.x - 1) ? 1 : 0;
    __syncthreads();
    if (!s_last) return;
    if (tid < NEXP) {
        int c = 0;
        const int4* p = (const int4*)g_part[tid];
        #pragma unroll 8
        for (int b = 0; b < NHBLK / 4; ++b) {
            int4 v = p[b];
            c += v.x + v.y + v.z + v.w;
        }
        s_cnt[tid] = c;
        g_counts[tid] = c;
    }
    __syncthreads();
    if (tid == 0) {
        int s = 0;
        #pragma unroll
        for (int e = 0; e < NEXP; ++e) {
            g_pbase[e]  = s;
            g_cursor[e] = s;
            s += ((s_cnt[e] + TILE_M - 1) / TILE_M) * TILE_M;
        }
        g_pbase[NEXP] = s;
        g_tick = 0;   // reset for next replay
    }
}

// ---------------- scatter (blocks < 512) + weight prep (blocks >= 512) ----
__global__ void k_scatter_prep(const int* __restrict__ pick,
                               const float* __restrict__ W1,
                               const float* __restrict__ W2,
                               const float* __restrict__ Wc1) {
    const int tid = threadIdx.x;
    if (blockIdx.x < NHBLK) {
        __shared__ int h[NEXP];
        __shared__ int base[NEXP];
        if (tid < NEXP) h[tid] = 0;
        __syncthreads();
        int n = blockIdx.x * blockDim.x + tid;
        int e = -1, r = 0;
        if (n < NTOK) { e = pick[n]; r = atomicAdd(&h[e], 1); }
        __syncthreads();
        if (tid < NEXP && h[tid] > 0) base[tid] = atomicAdd(&g_cursor[tid], h[tid]);
        __syncthreads();
        if (n < NTOK) g_sidx[base[e] + r] = n;
        return;
    }
    const int we = blockIdx.x - NHBLK;
    uint32_t* d1h = (uint32_t*)g_w1h + we * 8192;
    uint32_t* d1l = (uint32_t*)g_w1l + we * 8192;
    const float* w1p = (we < NEXP) ? W1 + (size_t)we * DDIM * HDIM : Wc1;
    for (int it = tid; it < 64 * 128; it += 256) {   // (kpair, n)
        int n = it & 127, kp = it >> 7, k0 = kp * 2;
        float a0 = (k0     < DDIM) ? w1p[k0 * HDIM + n]       : 0.0f;
        float a1 = (k0 + 1 < DDIM) ? w1p[(k0 + 1) * HDIM + n] : 0.0f;
        uint32_t hi, lo; cvt_hilo(a0, a1, hi, lo);
        uint32_t o4 = toff(n, k0) >> 2;
        d1h[o4] = hi; d1l[o4] = lo;
    }
    if (we < NEXP) {
        uint32_t* d2h = (uint32_t*)g_w2h + we * 1024;
        uint32_t* d2l = (uint32_t*)g_w2l + we * 1024;
        for (int it = tid; it < 16 * 64; it += 256) { // (o, jpair)
            int o = it >> 6, jp = it & 63, j0 = jp * 2;
            float a = W2[((size_t)we * HDIM + j0) * NACT + o];
            float b = W2[((size_t)we * HDIM + j0 + 1) * NACT + o];
            uint32_t hi, lo; cvt_hilo(a, b, hi, lo);
            uint32_t o4 = toff(o, j0) >> 2;
            d2h[o4] = hi; d2l[o4] = lo;
        }
    }
}

// ---------------- warp MMA helpers ----------------
__device__ __forceinline__ uint32_t smem_u32(const void* p) {
    uint32_t a;
    asm("{ .reg .u64 t; cvta.to.shared.u64 t, %1; cvt.u32.u64 %0, t; }"
        : "=r"(a) : "l"(p));
    return a;
}
__device__ __forceinline__ void ldsm4(uint32_t* r, uint32_t addr) {
    asm volatile("ldmatrix.sync.aligned.m8n8.x4.shared.b16 {%0,%1,%2,%3}, [%4];"
                 : "=r"(r[0]), "=r"(r[1]), "=r"(r[2]), "=r"(r[3]) : "r"(addr));
}
__device__ __forceinline__ void mma16816(float* d, const uint32_t* a,
                                         uint32_t b0, uint32_t b1) {
    asm volatile(
        "mma.sync.aligned.m16n8k16.row.col.f32.f16.f16.f32 "
        "{%0,%1,%2,%3}, {%4,%5,%6,%7}, {%8,%9}, {%0,%1,%2,%3};"
        : "+f"(d[0]), "+f"(d[1]), "+f"(d[2]), "+f"(d[3])
        : "r"(a[0]), "r"(a[1]), "r"(a[2]), "r"(a[3]), "r"(b0), "r"(b1));
}
#define CPA16(dst, src) \
    asm volatile("cp.async.cg.shared.global [%0], [%1], 16;" :: "r"(dst), "l"(src))
#define CPA_WAIT() \
    asm volatile("cp.async.commit_group;\ncp.async.wait_group 0;" ::: "memory")

// ---------------- fused main: one CTA = one (tile, net) pair ----------------
// blockIdx.x even -> actor tile, odd -> critic tile; tile = blockIdx.x >> 1.
// Warp grid 4x2: each warp m32 x n64 (R7 shape).
__global__ __launch_bounds__(256, 2)
void k_main(const float* __restrict__ obs,
            const int*   __restrict__ htype,
            const int*   __restrict__ gsel,
            const float* __restrict__ b1,  const float* __restrict__ b2,
            const float* __restrict__ bc1, const float* __restrict__ bc2,
            const float* __restrict__ Wc2,
            float* __restrict__ out) {
    extern __shared__ char dsm[];
    __shared__ __align__(1024) unsigned char s_w2h[16 * 256];
    __shared__ __align__(1024) unsigned char s_w2l[16 * 256];
    __shared__ float s_b1[HDIM], s_bc1[HDIM], s_wc2[HDIM], s_val[TILE_M], s_b2[NACT];
    __shared__ int   s_idx[TILE_M];

    const int tid    = threadIdx.x;
    const int wid    = tid >> 5;          // 0..7
    const int lane   = tid & 31;
    const int lane15 = lane & 15;
    const int laneh  = lane >> 4;
    const int g      = lane >> 2;
    const int q4     = lane & 3;
    const int tile   = blockIdx.x >> 1;
    const int isCr   = blockIdx.x & 1;
    const int ts     = tile * TILE_M;

    int e = -1;
    #pragma unroll
    for (int q = 0; q < NEXP; ++q)
        if (ts >= g_pbase[q] && ts < g_pbase[q + 1]) e = q;
    if (e < 0) return;
    const int lim = g_pbase[e] + g_counts[e];
    const uint32_t db = smem_u32(dsm);

    // ---- B tiles via cp.async (pre-swizzled fp16 hi/lo) ----
    {
        const int we = isCr ? NEXP : e;
        const uint4* sh = g_w1h + we * 2048;
        const uint4* sl = g_w1l + we * 2048;
        #pragma unroll
        for (int it = 0; it < 8; ++it) {
            int idx = tid + it * 256;
            CPA16(db + BH_OFF + idx * 16, sh + idx);
        }
        #pragma unroll
        for (int it = 0; it < 8; ++it) {
            int idx = tid + it * 256;
            CPA16(db + BL_OFF + idx * 16, sl + idx);
        }
        if (!isCr) {
            const uint32_t w2hA = smem_u32(s_w2h), w2lA = smem_u32(s_w2l);
            CPA16(w2hA + tid * 16, g_w2h + e * 256 + tid);
            CPA16(w2lA + tid * 16, g_w2l + e * 256 + tid);
        }
    }

    // ---- token indices + aug chunk (k=120..127, exact in fp16) + consts ----
    if (tid < TILE_M) {
        int gi  = ts + tid;
        int tok = (gi < lim) ? g_sidx[gi] : -1;
        s_idx[tid] = tok;
        uint4 a4 = {0u, 0u, 0u, 0u};
        if (tok >= 0) {
            int ht = htype[tok];
            int tI = tok >> 6;
            float av[6];
            av[0] = (float)ht;
            #pragma unroll
            for (int i = 0; i < NTP; ++i)
                av[1 + i] = (i == ht) ? -1.0f : (float)gsel[tI * NTP + i];
            a4.x = cvt_h2(av[0], av[1]);
            a4.y = cvt_h2(av[2], av[3]);
            a4.z = cvt_h2(av[4], av[5]);
        }
        *(uint4*)(dsm + A_OFF + tid * 256 + ((15 ^ (tid & 7)) << 4)) = a4;
        s_b1[tid]  = b1[e * HDIM + tid];
        s_bc1[tid] = bc1[tid];
        s_wc2[tid] = Wc2[tid];
        s_val[tid] = 0.0f;
    }
    if (tid < NACT) s_b2[tid] = b2[e * NACT + tid];
    __syncthreads();   // s_idx visible to all before A-stage

    // ---- A-stage: obs chunks (k = 0..119), single fp16 ----
    #pragma unroll
    for (int it = 0; it < 8; ++it) {
        int idx = tid + it * 256;            // (row, chunk) over 128x16
        int row = idx >> 4, c = idx & 15;
        if (c == 15) continue;               // aug chunk already written
        int tok = s_idx[row];
        uint4 a4 = {0u, 0u, 0u, 0u};
        if (tok >= 0) {
            const float4* src = (const float4*)(obs + (size_t)tok * RAWOB + c * 8);
            float4 f0 = src[0], f1 = src[1];
            a4.x = cvt_h2(f0.x, f0.y);
            a4.y = cvt_h2(f0.z, f0.w);
            a4.z = cvt_h2(f1.x, f1.y);
            a4.w = cvt_h2(f1.z, f1.w);
        }
        *(uint4*)(dsm + A_OFF + row * 256 + ((c ^ (row & 7)) << 4)) = a4;
    }
    CPA_WAIT();
    __syncthreads();

    // ---- mainloop: D = A*WH + A*WL ; warp tile m32 x n64 ----
    // BH+BL fragments loaded back-to-back (2 independent LDSM chains);
    // A fragments double-buffered across k-steps.
    const int m0 = (wid & 3) * 32;
    const int n0 = (wid >> 2) * 64;
    const int arow0 = m0 + lane15, arow1 = arow0 + 16;
    const uint32_t aoff0 = arow0 * 256, aoff1 = arow1 * 256;
    const int r7a0 = arow0 & 7, r7a1 = arow1 & 7;
    uint32_t boffv[4]; int r7b[4];
    #pragma unroll
    for (int qb = 0; qb < 4; ++qb) {
        int br = n0 + qb * 16 + lane15;
        boffv[qb] = br * 256; r7b[qb] = br & 7;
    }

    float acc[2][8][4];
    #pragma unroll
    for (int i = 0; i < 2; ++i)
        #pragma unroll
        for (int j = 0; j < 8; ++j)
            #pragma unroll
            for (int c = 0; c < 4; ++c) acc[i][j][c] = 0.0f;

    uint32_t afc[2][4], afn[2][4];
    {
        const int c0 = laneh;                 // ks = 0
        ldsm4(afc[0], db + A_OFF + aoff0 + (uint32_t)((c0 ^ r7a0) << 4));
        ldsm4(afc[1], db + A_OFF + aoff1 + (uint32_t)((c0 ^ r7a1) << 4));
    }
    #pragma unroll
    for (int ks = 0; ks < 8; ++ks) {
        const int c0 = 2 * ks + laneh;
        if (ks < 7) {
            const int c1 = 2 * (ks + 1) + laneh;
            ldsm4(afn[0], db + A_OFF + aoff0 + (uint32_t)((c1 ^ r7a0) << 4));
            ldsm4(afn[1], db + A_OFF + aoff1 + (uint32_t)((c1 ^ r7a1) << 4));
        }
        #pragma unroll
        for (int qb = 0; qb < 4; ++qb) {
            uint32_t bh[4], bl[4];
            const uint32_t co = (uint32_t)((c0 ^ r7b[qb]) << 4);
            ldsm4(bh, db + BH_OFF + boffv[qb] + co);
            ldsm4(bl, db + BL_OFF + boffv[qb] + co);
            mma16816(acc[0][2 * qb],     afc[0], bh[0], bh[2]);
            mma16816(acc[0][2 * qb + 1], afc[0], bh[1], bh[3]);
            mma16816(acc[1][2 * qb],     afc[1], bh[0], bh[2]);
            mma16816(acc[1][2 * qb + 1], afc[1], bh[1], bh[3]);
            mma16816(acc[0][2 * qb],     afc[0], bl[0], bl[2]);
            mma16816(acc[0][2 * qb + 1], afc[0], bl[1], bl[3]);
            mma16816(acc[1][2 * qb],     afc[1], bl[0], bl[2]);
            mma16816(acc[1][2 * qb + 1], afc[1], bl[1], bl[3]);
        }
        if (ks < 7) {
            #pragma unroll
            for (int i = 0; i < 2; ++i)
                #pragma unroll
                for (int j = 0; j < 4; ++j) afc[i][j] = afn[i][j];
        }
    }
    __syncthreads();   // all A/B reads done

    if (isCr) {
        // ---- critic epilogue: value from fp32 accumulators ----
        #pragma unroll
        for (int mt = 0; mt < 2; ++mt) {
            float p0 = 0.0f, p1 = 0.0f;
            #pragma unroll
            for (int nf = 0; nf < 8; ++nf) {
                const int col = n0 + 8 * nf + 2 * q4;
                const float w0 = s_wc2[col], w1 = s_wc2[col + 1];
                const float c0v = s_bc1[col], c1v = s_bc1[col + 1];
                p0 += fmaxf(acc[mt][nf][0] + c0v, 0.0f) * w0
                    + fmaxf(acc[mt][nf][1] + c1v, 0.0f) * w1;
                p1 += fmaxf(acc[mt][nf][2] + c0v, 0.0f) * w0
                    + fmaxf(acc[mt][nf][3] + c1v, 0.0f) * w1;
            }
            p0 += __shfl_xor_sync(0xffffffffu, p0, 1);
            p0 += __shfl_xor_sync(0xffffffffu, p0, 2);
            p1 += __shfl_xor_sync(0xffffffffu, p1, 1);
            p1 += __shfl_xor_sync(0xffffffffu, p1, 2);
            if (q4 == 0) {
                atomicAdd(&s_val[m0 + 16 * mt + g],     p0);
                atomicAdd(&s_val[m0 + 16 * mt + g + 8], p1);
            }
        }
        __syncthreads();
        if (tid < TILE_M) {
            int tok = s_idx[tid];
            if (tok >= 0) out[(size_t)NTOK * NACT + tok] = s_val[tid] + bc2[0];
        }
        return;
    }

    // ---- actor: hidden writeback (hi -> A region, lo -> BH region) ----
    #pragma unroll
    for (int mt = 0; mt < 2; ++mt) {
        #pragma unroll
        for (int nf = 0; nf < 8; ++nf) {
            const int col = n0 + 8 * nf + 2 * q4;
            const float bA = s_b1[col], bBv = s_b1[col + 1];
            const int r0 = m0 + 16 * mt + g, r1 = r0 + 8;
            uint32_t hi, lo;
            cvt_hilo(fmaxf(acc[mt][nf][0] + bA, 0.0f),
                     fmaxf(acc[mt][nf][1] + bBv, 0.0f), hi, lo);
            uint32_t off = toff(r0, col);
            *(uint32_t*)(dsm + A_OFF + off)  = hi;
            *(uint32_t*)(dsm + BH_OFF + off) = lo;
            cvt_hilo(fmaxf(acc[mt][nf][2] + bA, 0.0f),
                     fmaxf(acc[mt][nf][3] + bBv, 0.0f), hi, lo);
            off = toff(r1, col);
            *(uint32_t*)(dsm + A_OFF + off)  = hi;
            *(uint32_t*)(dsm + BH_OFF + off) = lo;
        }
    }
    __syncthreads();

    // ---- actor phase 2: logits = h @ W2 + b2 (3 passes: hh*wh + hh*wl + hl*wh)
    {
        const int arow = wid * 16 + lane15;
        const uint32_t aoff = arow * 256;
        const int r7 = arow & 7;
        const uint32_t boffp = lane15 * 256;
        const int r7p = lane15 & 7;
        const uint32_t w2hA = smem_u32(s_w2h), w2lA = smem_u32(s_w2l);
        const uint32_t aP[3] = {db + A_OFF, db + A_OFF, db + BH_OFF};
        const uint32_t bP[3] = {w2hA, w2lA, w2hA};

        float ac2[2][4];
        #pragma unroll
        for (int i = 0; i < 2; ++i)
            #pragma unroll
            for (int c = 0; c < 4; ++c) ac2[i][c] = 0.0f;

        #pragma unroll
        for (int p = 0; p < 3; ++p) {
            #pragma unroll
            for (int ks = 0; ks < 8; ++ks) {
                const int c0 = 2 * ks + laneh;
                uint32_t af[4], bf[4];
                ldsm4(af, aP[p] + aoff + (uint32_t)((c0 ^ r7) << 4));
                ldsm4(bf, bP[p] + boffp + (uint32_t)((c0 ^ r7p) << 4));
                mma16816(ac2[0], af, bf[0], bf[2]);
                mma16816(ac2[1], af, bf[1], bf[3]);
            }
        }

        const int r0 = wid * 16 + g, r1 = r0 + 8;
        const int tok0 = s_idx[r0], tok1 = s_idx[r1];
        #pragma unroll
        for (int nf = 0; nf < 2; ++nf) {
            const int cl = 8 * nf + 2 * q4;
            const float bA = s_b2[cl], bBv = s_b2[cl + 1];
            if (tok0 >= 0) {
                float2 v = {ac2[nf][0] + bA, ac2[nf][1] + bBv};
                *(float2*)(out + (size_t)tok0 * NACT + cl) = v;
            }
            if (tok1 >= 0) {
                float2 v = {ac2[nf][2] + bA, ac2[nf][3] + bBv};
                *(float2*)(out + (size_t)tok1 * NACT + cl) = v;
            }
        }
    }
}

// ---------------- launch ----------------
extern "C" void kernel_launch(void* const* d_in, const int* in_sizes, int n_in,
                              void* d_out, int out_size) {
    const float* obs   = (const float*)d_in[0];
    const int*   pick  = (const int*)  d_in[1];
    const int*   htype = (const int*)  d_in[2];
    const int*   gsel  = (const int*)  d_in[3];
    const float* W1    = (const float*)d_in[4];
    const float* b1    = (const float*)d_in[5];
    const float* W2    = (const float*)d_in[6];
    const float* b2    = (const float*)d_in[7];
    const float* Wc1   = (const float*)d_in[8];
    const float* bc1   = (const float*)d_in[9];
    const float* Wc2   = (const float*)d_in[10];
    const float* bc2   = (const float*)d_in[11];
    float* out = (float*)d_out;

    cudaFuncSetAttribute(k_main, cudaFuncAttributeMaxDynamicSharedMemorySize, DYN_SMEM);

    k_histscan    <<<NHBLK, 256>>>(pick);
    k_scatter_prep<<<NHBLK + NEXP + 1, 256>>>(pick, W1, W2, Wc1);
    k_main        <<<2 * NTILES, 256, DYN_SMEM>>>(obs, htype, gsel,
                                                  b1, b2, bc1, bc2, Wc2, out);
}

// round 14
// speedup vs baseline: 1.2823x; 1.2823x over previous
#include <cuda_runtime.h>
#include <cuda_fp16.h>
#include <cstdint>

// ---------------- problem constants ----------------
#define NTOK   131072
#define RAWOB  120
#define NTP    5
#define NEXP   10
#define DDIM   126
#define HDIM   128
#define NACT   16
#define TILE_M 128
#define NPAD   (NTOK + NEXP * TILE_M) // 132352
#define NTILES (NPAD / TILE_M)        // 1034

// dynamic smem: two 128x128 fp16 tiles (32KB each)
#define A_OFF   0
#define B_OFF   32768
#define DYN_SMEM 65536

// ---------------- scratch ----------------
__device__ int g_counts[NEXP];
__device__ int g_cursor[NEXP];
__device__ int g_pbase[NEXP + 1];
__device__ int g_sidx[NPAD];
__device__ unsigned int g_tick;

// pre-swizzled fp16 weight tiles; slot NEXP = critic Wc1
__device__ uint4 g_w1[(NEXP + 1) * 2048];   // 32KB per net (single fp16)
__device__ uint4 g_w2h[NEXP * 256];         // 4KB per expert (16x128)
__device__ uint4 g_w2l[NEXP * 256];

// tile element byte offset: 256B rows, 16B chunks XOR-swizzled by row
__device__ __forceinline__ uint32_t toff(int row, int k) {
    return (uint32_t)(row * 256 + (((k >> 3) ^ (row & 7)) << 4) + (k & 7) * 2);
}
__device__ __forceinline__ void cvt_hilo(float a, float b, uint32_t& hi, uint32_t& lo) {
    __half2 h2 = __floats2half2_rn(a, b);
    float2 bk = __half22float2(h2);
    __half2 l2 = __floats2half2_rn(a - bk.x, b - bk.y);
    hi = reinterpret_cast<uint32_t&>(h2);
    lo = reinterpret_cast<uint32_t&>(l2);
}
__device__ __forceinline__ uint32_t cvt_h2(float a, float b) {
    __half2 h2 = __floats2half2_rn(a, b);
    return reinterpret_cast<uint32_t&>(h2);
}

// ---------------- k_init ----------------
__global__ void k_init() {
    int i = threadIdx.x;
    if (i < NEXP) { g_counts[i] = 0; g_cursor[i] = 0; }
    if (i == 31) g_tick = 0;
}

// ---------------- hist + scan (ticket)  [R7-exact] ----------------
__global__ void k_histscan(const int* __restrict__ pick) {
    __shared__ int h[NEXP];
    int tid = threadIdx.x;
    if (tid < NEXP) h[tid] = 0;
    __syncthreads();
    int n = blockIdx.x * blockDim.x + tid;
    if (n < NTOK) atomicAdd(&h[pick[n]], 1);
    __syncthreads();
    if (tid < NEXP && h[tid] > 0) atomicAdd(&g_counts[tid], h[tid]);
    __threadfence();
    __syncthreads();
    if (tid == 0) {
        if (atomicAdd(&g_tick, 1u) == gridDim.x - 1) {
            int s = 0;
            for (int e = 0; e < NEXP; ++e) {
                g_pbase[e]  = s;
                g_cursor[e] = s;
                int c = g_counts[e];
                s += ((c + TILE_M - 1) / TILE_M) * TILE_M;
            }
            g_pbase[NEXP] = s;
            g_tick = 0;
        }
    }
}

// ---------------- scatter (blocks < 512) + weight prep (blocks >= 512) ----
__global__ void k_scatter_prep(const int* __restrict__ pick,
                               const float* __restrict__ W1,
                               const float* __restrict__ W2,
                               const float* __restrict__ Wc1) {
    const int tid = threadIdx.x;
    if (blockIdx.x < 512) {
        __shared__ int h[NEXP];
        __shared__ int base[NEXP];
        if (tid < NEXP) h[tid] = 0;
        __syncthreads();
        int n = blockIdx.x * blockDim.x + tid;
        int e = -1, r = 0;
        if (n < NTOK) { e = pick[n]; r = atomicAdd(&h[e], 1); }
        __syncthreads();
        if (tid < NEXP && h[tid] > 0) base[tid] = atomicAdd(&g_cursor[tid], h[tid]);
        __syncthreads();
        if (n < NTOK) g_sidx[base[e] + r] = n;
        return;
    }
    const int we = blockIdx.x - 512;
    uint32_t* d1 = (uint32_t*)g_w1 + we * 8192;
    const float* w1p = (we < NEXP) ? W1 + (size_t)we * DDIM * HDIM : Wc1;
    for (int it = tid; it < 64 * 128; it += 256) {   // (kpair, n)
        int n = it & 127, kp = it >> 7, k0 = kp * 2;
        float a0 = (k0     < DDIM) ? w1p[k0 * HDIM + n]       : 0.0f;
        float a1 = (k0 + 1 < DDIM) ? w1p[(k0 + 1) * HDIM + n] : 0.0f;
        d1[toff(n, k0) >> 2] = cvt_h2(a0, a1);
    }
    if (we < NEXP) {
        uint32_t* d2h = (uint32_t*)g_w2h + we * 1024;
        uint32_t* d2l = (uint32_t*)g_w2l + we * 1024;
        for (int it = tid; it < 16 * 64; it += 256) { // (o, jpair)
            int o = it >> 6, jp = it & 63, j0 = jp * 2;
            float a = W2[((size_t)we * HDIM + j0) * NACT + o];
            float b = W2[((size_t)we * HDIM + j0 + 1) * NACT + o];
            uint32_t hi, lo; cvt_hilo(a, b, hi, lo);
            uint32_t o4 = toff(o, j0) >> 2;
            d2h[o4] = hi; d2l[o4] = lo;
        }
    }
}

// ---------------- warp MMA helpers ----------------
__device__ __forceinline__ uint32_t smem_u32(const void* p) {
    uint32_t a;
    asm("{ .reg .u64 t; cvta.to.shared.u64 t, %1; cvt.u32.u64 %0, t; }"
        : "=r"(a) : "l"(p));
    return a;
}
__device__ __forceinline__ void ldsm4(uint32_t* r, uint32_t addr) {
    asm volatile("ldmatrix.sync.aligned.m8n8.x4.shared.b16 {%0,%1,%2,%3}, [%4];"
                 : "=r"(r[0]), "=r"(r[1]), "=r"(r[2]), "=r"(r[3]) : "r"(addr));
}
__device__ __forceinline__ void mma16816(float* d, const uint32_t* a,
                                         uint32_t b0, uint32_t b1) {
    asm volatile(
        "mma.sync.aligned.m16n8k16.row.col.f32.f16.f16.f32 "
        "{%0,%1,%2,%3}, {%4,%5,%6,%7}, {%8,%9}, {%0,%1,%2,%3};"
        : "+f"(d[0]), "+f"(d[1]), "+f"(d[2]), "+f"(d[3])
        : "r"(a[0]), "r"(a[1]), "r"(a[2]), "r"(a[3]), "r"(b0), "r"(b1));
}
#define CPA16(dst, src) \
    asm volatile("cp.async.cg.shared.global [%0], [%1], 16;" :: "r"(dst), "l"(src))
#define CPA_WAIT() \
    asm volatile("cp.async.commit_group;\ncp.async.wait_group 0;" ::: "memory")

// ---------------- fused main: one CTA = one (tile, net) pair ----------------
// blockIdx.x even -> actor tile, odd -> critic tile; tile = blockIdx.x >> 1.
// Warp grid 4x2: each warp m32 x n64 (R7 shape). Single-fp16 W1 (one pass).
__global__ __launch_bounds__(256, 2)
void k_main(const float* __restrict__ obs,
            const int*   __restrict__ htype,
            const int*   __restrict__ gsel,
            const float* __restrict__ b1,  const float* __restrict__ b2,
            const float* __restrict__ bc1, const float* __restrict__ bc2,
            const float* __restrict__ Wc2,
            float* __restrict__ out) {
    extern __shared__ char dsm[];
    __shared__ __align__(1024) unsigned char s_w2h[16 * 256];
    __shared__ __align__(1024) unsigned char s_w2l[16 * 256];
    __shared__ float s_b1[HDIM], s_bc1[HDIM], s_wc2[HDIM], s_val[TILE_M], s_b2[NACT];
    __shared__ int   s_idx[TILE_M];

    const int tid    = threadIdx.x;
    const int wid    = tid >> 5;          // 0..7
    const int lane   = tid & 31;
    const int lane15 = lane & 15;
    const int laneh  = lane >> 4;
    const int g      = lane >> 2;
    const int q4     = lane & 3;
    const int tile   = blockIdx.x >> 1;
    const int isCr   = blockIdx.x & 1;
    const int ts     = tile * TILE_M;

    int e = -1;
    #pragma unroll
    for (int q = 0; q < NEXP; ++q)
        if (ts >= g_pbase[q] && ts < g_pbase[q + 1]) e = q;
    if (e < 0) return;
    const int lim = g_pbase[e] + g_counts[e];
    const uint32_t db = smem_u32(dsm);

    // ---- B tile via cp.async (pre-swizzled single fp16) ----
    {
        const uint4* sw = g_w1 + (isCr ? NEXP : e) * 2048;
        #pragma unroll
        for (int it = 0; it < 8; ++it) {
            int idx = tid + it * 256;
            CPA16(db + B_OFF + idx * 16, sw + idx);
        }
        if (!isCr) {
            const uint32_t w2hA = smem_u32(s_w2h), w2lA = smem_u32(s_w2l);
            CPA16(w2hA + tid * 16, g_w2h + e * 256 + tid);
            CPA16(w2lA + tid * 16, g_w2l + e * 256 + tid);
        }
    }

    // ---- token indices + aug chunk (k=120..127, exact in fp16) + consts ----
    if (tid < TILE_M) {
        int gi  = ts + tid;
        int tok = (gi < lim) ? g_sidx[gi] : -1;
        s_idx[tid] = tok;
        uint4 a4 = {0u, 0u, 0u, 0u};
        if (tok >= 0) {
            int ht = htype[tok];
            int tI = tok >> 6;
            float av[6];
            av[0] = (float)ht;
            #pragma unroll
            for (int i = 0; i < NTP; ++i)
                av[1 + i] = (i == ht) ? -1.0f : (float)gsel[tI * NTP + i];
            a4.x = cvt_h2(av[0], av[1]);
            a4.y = cvt_h2(av[2], av[3]);
            a4.z = cvt_h2(av[4], av[5]);
        }
        *(uint4*)(dsm + A_OFF + tid * 256 + ((15 ^ (tid & 7)) << 4)) = a4;
        s_b1[tid]  = b1[e * HDIM + tid];
        s_bc1[tid] = bc1[tid];
        s_wc2[tid] = Wc2[tid];
        s_val[tid] = 0.0f;
    }
    if (tid < NACT) s_b2[tid] = b2[e * NACT + tid];
    __syncthreads();   // s_idx visible to all before A-stage

    // ---- A-stage: obs chunks (k = 0..119), single fp16 ----
    #pragma unroll
    for (int it = 0; it < 8; ++it) {
        int idx = tid + it * 256;            // (row, chunk) over 128x16
        int row = idx >> 4, c = idx & 15;
        if (c == 15) continue;               // aug chunk already written
        int tok = s_idx[row];
        uint4 a4 = {0u, 0u, 0u, 0u};
        if (tok >= 0) {
            const float4* src = (const float4*)(obs + (size_t)tok * RAWOB + c * 8);
            float4 f0 = src[0], f1 = src[1];
            a4.x = cvt_h2(f0.x, f0.y);
            a4.y = cvt_h2(f0.z, f0.w);
            a4.z = cvt_h2(f1.x, f1.y);
            a4.w = cvt_h2(f1.z, f1.w);
        }
        *(uint4*)(dsm + A_OFF + row * 256 + ((c ^ (row & 7)) << 4)) = a4;
    }
    CPA_WAIT();
    __syncthreads();

    // ---- mainloop: D = A*W (single pass) ; warp tile m32 x n64 ----
    const int m0 = (wid & 3) * 32;
    const int n0 = (wid >> 2) * 64;
    const int arow0 = m0 + lane15, arow1 = arow0 + 16;
    const uint32_t aoff0 = arow0 * 256, aoff1 = arow1 * 256;
    const int r7a0 = arow0 & 7, r7a1 = arow1 & 7;
    uint32_t boffv[4]; int r7b[4];
    #pragma unroll
    for (int qb = 0; qb < 4; ++qb) {
        int br = n0 + qb * 16 + lane15;
        boffv[qb] = br * 256; r7b[qb] = br & 7;
    }

    float acc[2][8][4];
    #pragma unroll
    for (int i = 0; i < 2; ++i)
        #pragma unroll
        for (int j = 0; j < 8; ++j)
            #pragma unroll
            for (int c = 0; c < 4; ++c) acc[i][j][c] = 0.0f;

    #pragma unroll
    for (int ks = 0; ks < 8; ++ks) {
        const int c0 = 2 * ks + laneh;
        uint32_t af0[4], af1[4];
        ldsm4(af0, db + A_OFF + aoff0 + (uint32_t)((c0 ^ r7a0) << 4));
        ldsm4(af1, db + A_OFF + aoff1 + (uint32_t)((c0 ^ r7a1) << 4));
        #pragma unroll
        for (int qb = 0; qb < 4; ++qb) {
            uint32_t bf[4];
            ldsm4(bf, db + B_OFF + boffv[qb] + (uint32_t)((c0 ^ r7b[qb]) << 4));
            mma16816(acc[0][2 * qb],     af0, bf[0], bf[2]);
            mma16816(acc[0][2 * qb + 1], af0, bf[1], bf[3]);
            mma16816(acc[1][2 * qb],     af1, bf[0], bf[2]);
            mma16816(acc[1][2 * qb + 1], af1, bf[1], bf[3]);
        }
    }
    __syncthreads();   // all A/B reads done

    if (isCr) {
        // ---- critic epilogue: value from fp32 accumulators ----
        #pragma unroll
        for (int mt = 0; mt < 2; ++mt) {
            float p0 = 0.0f, p1 = 0.0f;
            #pragma unroll
            for (int nf = 0; nf < 8; ++nf) {
                const int col = n0 + 8 * nf + 2 * q4;
                const float w0 = s_wc2[col], w1 = s_wc2[col + 1];
                const float c0v = s_bc1[col], c1v = s_bc1[col + 1];
                p0 += fmaxf(acc[mt][nf][0] + c0v, 0.0f) * w0
                    + fmaxf(acc[mt][nf][1] + c1v, 0.0f) * w1;
                p1 += fmaxf(acc[mt][nf][2] + c0v, 0.0f) * w0
                    + fmaxf(acc[mt][nf][3] + c1v, 0.0f) * w1;
            }
            p0 += __shfl_xor_sync(0xffffffffu, p0, 1);
            p0 += __shfl_xor_sync(0xffffffffu, p0, 2);
            p1 += __shfl_xor_sync(0xffffffffu, p1, 1);
            p1 += __shfl_xor_sync(0xffffffffu, p1, 2);
            if (q4 == 0) {
                atomicAdd(&s_val[m0 + 16 * mt + g],     p0);
                atomicAdd(&s_val[m0 + 16 * mt + g + 8], p1);
            }
        }
        __syncthreads();
        if (tid < TILE_M) {
            int tok = s_idx[tid];
            if (tok >= 0) out[(size_t)NTOK * NACT + tok] = s_val[tid] + bc2[0];
        }
        return;
    }

    // ---- actor: hidden writeback (hi -> A region, lo -> B region) ----
    #pragma unroll
    for (int mt = 0; mt < 2; ++mt) {
        #pragma unroll
        for (int nf = 0; nf < 8; ++nf) {
            const int col = n0 + 8 * nf + 2 * q4;
            const float bA = s_b1[col], bBv = s_b1[col + 1];
            const int r0 = m0 + 16 * mt + g, r1 = r0 + 8;
            uint32_t hi, lo;
            cvt_hilo(fmaxf(acc[mt][nf][0] + bA, 0.0f),
                     fmaxf(acc[mt][nf][1] + bBv, 0.0f), hi, lo);
            uint32_t off = toff(r0, col);
            *(uint32_t*)(dsm + A_OFF + off) = hi;
            *(uint32_t*)(dsm + B_OFF + off) = lo;
            cvt_hilo(fmaxf(acc[mt][nf][2] + bA, 0.0f),
                     fmaxf(acc[mt][nf][3] + bBv, 0.0f), hi, lo);
            off = toff(r1, col);
            *(uint32_t*)(dsm + A_OFF + off) = hi;
            *(uint32_t*)(dsm + B_OFF + off) = lo;
        }
    }
    __syncthreads();

    // ---- actor phase 2: logits = h @ W2 + b2 (3 passes: hh*wh + hh*wl + hl*wh)
    {
        const int arow = wid * 16 + lane15;
        const uint32_t aoff = arow * 256;
        const int r7 = arow & 7;
        const uint32_t boffp = lane15 * 256;
        const int r7p = lane15 & 7;
        const uint32_t w2hA = smem_u32(s_w2h), w2lA = smem_u32(s_w2l);
        const uint32_t aP[3] = {db + A_OFF, db + A_OFF, db + B_OFF};
        const uint32_t bP[3] = {w2hA, w2lA, w2hA};

        float ac2[2][4];
        #pragma unroll
        for (int i = 0; i < 2; ++i)
            #pragma unroll
            for (int c = 0; c < 4; ++c) ac2[i][c] = 0.0f;

        #pragma unroll
        for (int p = 0; p < 3; ++p) {
            #pragma unroll
            for (int ks = 0; ks < 8; ++ks) {
                const int c0 = 2 * ks + laneh;
                uint32_t af[4], bf[4];
                ldsm4(af, aP[p] + aoff + (uint32_t)((c0 ^ r7) << 4));
                ldsm4(bf, bP[p] + boffp + (uint32_t)((c0 ^ r7p) << 4));
                mma16816(ac2[0], af, bf[0], bf[2]);
                mma16816(ac2[1], af, bf[1], bf[3]);
            }
        }

        const int r0 = wid * 16 + g, r1 = r0 + 8;
        const int tok0 = s_idx[r0], tok1 = s_idx[r1];
        #pragma unroll
        for (int nf = 0; nf < 2; ++nf) {
            const int cl = 8 * nf + 2 * q4;
            const float bA = s_b2[cl], bBv = s_b2[cl + 1];
            if (tok0 >= 0) {
                float2 v = {ac2[nf][0] + bA, ac2[nf][1] + bBv};
                *(float2*)(out + (size_t)tok0 * NACT + cl) = v;
            }
            if (tok1 >= 0) {
                float2 v = {ac2[nf][2] + bA, ac2[nf][3] + bBv};
                *(float2*)(out + (size_t)tok1 * NACT + cl) = v;
            }
        }
    }
}

// ---------------- launch ----------------
extern "C" void kernel_launch(void* const* d_in, const int* in_sizes, int n_in,
                              void* d_out, int out_size) {
    const float* obs   = (const float*)d_in[0];
    const int*   pick  = (const int*)  d_in[1];
    const int*   htype = (const int*)  d_in[2];
    const int*   gsel  = (const int*)  d_in[3];
    const float* W1    = (const float*)d_in[4];
    const float* b1    = (const float*)d_in[5];
    const float* W2    = (const float*)d_in[6];
    const float* b2    = (const float*)d_in[7];
    const float* Wc1   = (const float*)d_in[8];
    const float* bc1   = (const float*)d_in[9];
    const float* Wc2   = (const float*)d_in[10];
    const float* bc2   = (const float*)d_in[11];
    float* out = (float*)d_out;

    cudaFuncSetAttribute(k_main, cudaFuncAttributeMaxDynamicSharedMemorySize, DYN_SMEM);

    k_init        <<<1, 32>>>();
    k_histscan    <<<512, 256>>>(pick);
    k_scatter_prep<<<512 + NEXP + 1, 256>>>(pick, W1, W2, Wc1);
    k_main        <<<2 * NTILES, 256, DYN_SMEM>>>(obs, htype, gsel,
                                                  b1, b2, bc1, bc2, Wc2, out);
}

// round 17
// speedup vs baseline: 1.3248x; 1.0331x over previous
#include <cuda_runtime.h>
#include <cuda_fp16.h>
#include <cstdint>

// ---------------- problem constants ----------------
#define NTOK   131072
#define RAWOB  120
#define NTP    5
#define NEXP   10
#define DDIM   126
#define HDIM   128
#define NACT   16
#define TILE_M 128
#define NPAD   (NTOK + NEXP * TILE_M) // 132352
#define NTILES (NPAD / TILE_M)        // 1034

// dynamic smem: two 128x128 fp16 tiles (32KB each)
#define A_OFF   0
#define B_OFF   32768
#define DYN_SMEM 65536

// ---------------- scratch ----------------
__device__ int g_counts[NEXP];
__device__ int g_cursor[NEXP];
__device__ int g_pbase[NEXP + 1];
__device__ int g_sidx[NPAD];
__device__ unsigned int g_tick;

// pre-swizzled fp16 weight tiles; slot NEXP = critic Wc1
__device__ uint4 g_w1[(NEXP + 1) * 2048];   // 32KB per net (single fp16)
__device__ uint4 g_w2h[NEXP * 256];         // 4KB per expert (16x128)
__device__ uint4 g_w2l[NEXP * 256];

// tile element byte offset: 256B rows, 16B chunks XOR-swizzled by row
__device__ __forceinline__ uint32_t toff(int row, int k) {
    return (uint32_t)(row * 256 + (((k >> 3) ^ (row & 7)) << 4) + (k & 7) * 2);
}
__device__ __forceinline__ void cvt_hilo(float a, float b, uint32_t& hi, uint32_t& lo) {
    __half2 h2 = __floats2half2_rn(a, b);
    float2 bk = __half22float2(h2);
    __half2 l2 = __floats2half2_rn(a - bk.x, b - bk.y);
    hi = reinterpret_cast<uint32_t&>(h2);
    lo = reinterpret_cast<uint32_t&>(l2);
}
__device__ __forceinline__ uint32_t cvt_h2(float a, float b) {
    __half2 h2 = __floats2half2_rn(a, b);
    return reinterpret_cast<uint32_t&>(h2);
}

// ---------------- k_init ----------------
__global__ void k_init() {
    int i = threadIdx.x;
    if (i < NEXP) { g_counts[i] = 0; g_cursor[i] = 0; }
    if (i == 31) g_tick = 0;
}

// ---------------- hist + scan (ticket)  [R7-exact] ----------------
__global__ void k_histscan(const int* __restrict__ pick) {
    __shared__ int h[NEXP];
    int tid = threadIdx.x;
    if (tid < NEXP) h[tid] = 0;
    __syncthreads();
    int n = blockIdx.x * blockDim.x + tid;
    if (n < NTOK) atomicAdd(&h[pick[n]], 1);
    __syncthreads();
    if (tid < NEXP && h[tid] > 0) atomicAdd(&g_counts[tid], h[tid]);
    __threadfence();
    __syncthreads();
    if (tid == 0) {
        if (atomicAdd(&g_tick, 1u) == gridDim.x - 1) {
            int s = 0;
            for (int e = 0; e < NEXP; ++e) {
                g_pbase[e]  = s;
                g_cursor[e] = s;
                int c = g_counts[e];
                s += ((c + TILE_M - 1) / TILE_M) * TILE_M;
            }
            g_pbase[NEXP] = s;
            g_tick = 0;
        }
    }
}

// ---------------- scatter (blocks < 512) + weight prep (blocks >= 512) ----
__global__ void k_scatter_prep(const int* __restrict__ pick,
                               const float* __restrict__ W1,
                               const float* __restrict__ W2,
                               const float* __restrict__ Wc1) {
    const int tid = threadIdx.x;
    if (blockIdx.x < 512) {
        __shared__ int h[NEXP];
        __shared__ int base[NEXP];
        if (tid < NEXP) h[tid] = 0;
        __syncthreads();
        int n = blockIdx.x * blockDim.x + tid;
        int e = -1, r = 0;
        if (n < NTOK) { e = pick[n]; r = atomicAdd(&h[e], 1); }
        __syncthreads();
        if (tid < NEXP && h[tid] > 0) base[tid] = atomicAdd(&g_cursor[tid], h[tid]);
        __syncthreads();
        if (n < NTOK) g_sidx[base[e] + r] = n;
        return;
    }
    const int we = blockIdx.x - 512;
    uint32_t* d1 = (uint32_t*)g_w1 + we * 8192;
    const float* w1p = (we < NEXP) ? W1 + (size_t)we * DDIM * HDIM : Wc1;
    for (int it = tid; it < 64 * 128; it += 256) {   // (kpair, n)
        int n = it & 127, kp = it >> 7, k0 = kp * 2;
        float a0 = (k0     < DDIM) ? w1p[k0 * HDIM + n]       : 0.0f;
        float a1 = (k0 + 1 < DDIM) ? w1p[(k0 + 1) * HDIM + n] : 0.0f;
        d1[toff(n, k0) >> 2] = cvt_h2(a0, a1);
    }
    if (we < NEXP) {
        uint32_t* d2h = (uint32_t*)g_w2h + we * 1024;
        uint32_t* d2l = (uint32_t*)g_w2l + we * 1024;
        for (int it = tid; it < 16 * 64; it += 256) { // (o, jpair)
            int o = it >> 6, jp = it & 63, j0 = jp * 2;
            float a = W2[((size_t)we * HDIM + j0) * NACT + o];
            float b = W2[((size_t)we * HDIM + j0 + 1) * NACT + o];
            uint32_t hi, lo; cvt_hilo(a, b, hi, lo);
            uint32_t o4 = toff(o, j0) >> 2;
            d2h[o4] = hi; d2l[o4] = lo;
        }
    }
}

// ---------------- warp MMA helpers ----------------
__device__ __forceinline__ uint32_t smem_u32(const void* p) {
    uint32_t a;
    asm("{ .reg .u64 t; cvta.to.shared.u64 t, %1; cvt.u32.u64 %0, t; }"
        : "=r"(a) : "l"(p));
    return a;
}
__device__ __forceinline__ void ldsm4(uint32_t* r, uint32_t addr) {
    asm volatile("ldmatrix.sync.aligned.m8n8.x4.shared.b16 {%0,%1,%2,%3}, [%4];"
                 : "=r"(r[0]), "=r"(r[1]), "=r"(r[2]), "=r"(r[3]) : "r"(addr));
}
__device__ __forceinline__ void mma16816(float* d, const uint32_t* a,
                                         uint32_t b0, uint32_t b1) {
    asm volatile(
        "mma.sync.aligned.m16n8k16.row.col.f32.f16.f16.f32 "
        "{%0,%1,%2,%3}, {%4,%5,%6,%7}, {%8,%9}, {%0,%1,%2,%3};"
        : "+f"(d[0]), "+f"(d[1]), "+f"(d[2]), "+f"(d[3])
        : "r"(a[0]), "r"(a[1]), "r"(a[2]), "r"(a[3]), "r"(b0), "r"(b1));
}
#define CPA16(dst, src) \
    asm volatile("cp.async.cg.shared.global [%0], [%1], 16;" :: "r"(dst), "l"(src))
#define CPA_WAIT() \
    asm volatile("cp.async.commit_group;\ncp.async.wait_group 0;" ::: "memory")

// ---------------- fused main: one CTA = one (tile, net) pair ----------------
// blockIdx.x even -> actor tile, odd -> critic tile; tile = blockIdx.x >> 1.
// Warp grid 4x2: each warp m32 x n64. Single-fp16 W1 mainloop (one pass).
// Phase 2: hidden single fp16, W2 hi/lo exact (2 passes, A fragment shared).
__global__ __launch_bounds__(256, 2)
void k_main(const float* __restrict__ obs,
            const int*   __restrict__ htype,
            const int*   __restrict__ gsel,
            const float* __restrict__ b1,  const float* __restrict__ b2,
            const float* __restrict__ bc1, const float* __restrict__ bc2,
            const float* __restrict__ Wc2,
            float* __restrict__ out) {
    extern __shared__ char dsm[];
    __shared__ __align__(1024) unsigned char s_w2h[16 * 256];
    __shared__ __align__(1024) unsigned char s_w2l[16 * 256];
    __shared__ float s_b1[HDIM], s_bc1[HDIM], s_wc2[HDIM], s_val[TILE_M], s_b2[NACT];
    __shared__ int   s_idx[TILE_M];

    const int tid    = threadIdx.x;
    const int wid    = tid >> 5;          // 0..7
    const int lane   = tid & 31;
    const int lane15 = lane & 15;
    const int laneh  = lane >> 4;
    const int g      = lane >> 2;
    const int q4     = lane & 3;
    const int tile   = blockIdx.x >> 1;
    const int isCr   = blockIdx.x & 1;
    const int ts     = tile * TILE_M;

    int e = -1;
    #pragma unroll
    for (int q = 0; q < NEXP; ++q)
        if (ts >= g_pbase[q] && ts < g_pbase[q + 1]) e = q;
    if (e < 0) return;
    const int lim = g_pbase[e] + g_counts[e];
    const uint32_t db = smem_u32(dsm);

    // ---- B tile via cp.async (pre-swizzled single fp16) ----
    {
        const uint4* sw = g_w1 + (isCr ? NEXP : e) * 2048;
        #pragma unroll
        for (int it = 0; it < 8; ++it) {
            int idx = tid + it * 256;
            CPA16(db + B_OFF + idx * 16, sw + idx);
        }
        if (!isCr) {
            const uint32_t w2hA = smem_u32(s_w2h), w2lA = smem_u32(s_w2l);
            CPA16(w2hA + tid * 16, g_w2h + e * 256 + tid);
            CPA16(w2lA + tid * 16, g_w2l + e * 256 + tid);
        }
    }

    // ---- token indices + aug chunk (k=120..127, exact in fp16) + consts ----
    if (tid < TILE_M) {
        int gi  = ts + tid;
        int tok = (gi < lim) ? g_sidx[gi] : -1;
        s_idx[tid] = tok;
        uint4 a4 = {0u, 0u, 0u, 0u};
        if (tok >= 0) {
            int ht = htype[tok];
            int tI = tok >> 6;
            float av[6];
            av[0] = (float)ht;
            #pragma unroll
            for (int i = 0; i < NTP; ++i)
                av[1 + i] = (i == ht) ? -1.0f : (float)gsel[tI * NTP + i];
            a4.x = cvt_h2(av[0], av[1]);
            a4.y = cvt_h2(av[2], av[3]);
            a4.z = cvt_h2(av[4], av[5]);
        }
        *(uint4*)(dsm + A_OFF + tid * 256 + ((15 ^ (tid & 7)) << 4)) = a4;
        s_b1[tid]  = b1[e * HDIM + tid];
        s_bc1[tid] = bc1[tid];
        s_wc2[tid] = Wc2[tid];
        s_val[tid] = 0.0f;
    }
    if (tid < NACT) s_b2[tid] = b2[e * NACT + tid];
    __syncthreads();   // s_idx visible to all before A-stage

    // ---- A-stage: obs chunks (k = 0..119), single fp16 ----
    #pragma unroll
    for (int it = 0; it < 8; ++it) {
        int idx = tid + it * 256;            // (row, chunk) over 128x16
        int row = idx >> 4, c = idx & 15;
        if (c == 15) continue;               // aug chunk already written
        int tok = s_idx[row];
        uint4 a4 = {0u, 0u, 0u, 0u};
        if (tok >= 0) {
            const float4* src = (const float4*)(obs + (size_t)tok * RAWOB + c * 8);
            float4 f0 = src[0], f1 = src[1];
            a4.x = cvt_h2(f0.x, f0.y);
            a4.y = cvt_h2(f0.z, f0.w);
            a4.z = cvt_h2(f1.x, f1.y);
            a4.w = cvt_h2(f1.z, f1.w);
        }
        *(uint4*)(dsm + A_OFF + row * 256 + ((c ^ (row & 7)) << 4)) = a4;
    }
    CPA_WAIT();
    __syncthreads();

    // ---- mainloop: D = A*W (single pass) ; warp tile m32 x n64 ----
    const int m0 = (wid & 3) * 32;
    const int n0 = (wid >> 2) * 64;
    const int arow0 = m0 + lane15, arow1 = arow0 + 16;
    const uint32_t aoff0 = arow0 * 256, aoff1 = arow1 * 256;
    const int r7a0 = arow0 & 7, r7a1 = arow1 & 7;
    uint32_t boffv[4]; int r7b[4];
    #pragma unroll
    for (int qb = 0; qb < 4; ++qb) {
        int br = n0 + qb * 16 + lane15;
        boffv[qb] = br * 256; r7b[qb] = br & 7;
    }

    float acc[2][8][4];
    #pragma unroll
    for (int i = 0; i < 2; ++i)
        #pragma unroll
        for (int j = 0; j < 8; ++j)
            #pragma unroll
            for (int c = 0; c < 4; ++c) acc[i][j][c] = 0.0f;

    #pragma unroll
    for (int ks = 0; ks < 8; ++ks) {
        const int c0 = 2 * ks + laneh;
        uint32_t af0[4], af1[4];
        ldsm4(af0, db + A_OFF + aoff0 + (uint32_t)((c0 ^ r7a0) << 4));
        ldsm4(af1, db + A_OFF + aoff1 + (uint32_t)((c0 ^ r7a1) << 4));
        #pragma unroll
        for (int qb = 0; qb < 4; ++qb) {
            uint32_t bf[4];
            ldsm4(bf, db + B_OFF + boffv[qb] + (uint32_t)((c0 ^ r7b[qb]) << 4));
            mma16816(acc[0][2 * qb],     af0, bf[0], bf[2]);
            mma16816(acc[0][2 * qb + 1], af0, bf[1], bf[3]);
            mma16816(acc[1][2 * qb],     af1, bf[0], bf[2]);
            mma16816(acc[1][2 * qb + 1], af1, bf[1], bf[3]);
        }
    }
    __syncthreads();   // all A/B reads done

    if (isCr) {
        // ---- critic epilogue: value from fp32 accumulators ----
        #pragma unroll
        for (int mt = 0; mt < 2; ++mt) {
            float p0 = 0.0f, p1 = 0.0f;
            #pragma unroll
            for (int nf = 0; nf < 8; ++nf) {
                const int col = n0 + 8 * nf + 2 * q4;
                const float w0 = s_wc2[col], w1 = s_wc2[col + 1];
                const float c0v = s_bc1[col], c1v = s_bc1[col + 1];
                p0 += fmaxf(acc[mt][nf][0] + c0v, 0.0f) * w0
                    + fmaxf(acc[mt][nf][1] + c1v, 0.0f) * w1;
                p1 += fmaxf(acc[mt][nf][2] + c0v, 0.0f) * w0
                    + fmaxf(acc[mt][nf][3] + c1v, 0.0f) * w1;
            }
            p0 += __shfl_xor_sync(0xffffffffu, p0, 1);
            p0 += __shfl_xor_sync(0xffffffffu, p0, 2);
            p1 += __shfl_xor_sync(0xffffffffu, p1, 1);
            p1 += __shfl_xor_sync(0xffffffffu, p1, 2);
            if (q4 == 0) {
                atomicAdd(&s_val[m0 + 16 * mt + g],     p0);
                atomicAdd(&s_val[m0 + 16 * mt + g + 8], p1);
            }
        }
        __syncthreads();
        if (tid < TILE_M) {
            int tok = s_idx[tid];
            if (tok >= 0) out[(size_t)NTOK * NACT + tok] = s_val[tid] + bc2[0];
        }
        return;
    }

    // ---- actor: hidden writeback (single fp16 hi -> A region) ----
    #pragma unroll
    for (int mt = 0; mt < 2; ++mt) {
        #pragma unroll
        for (int nf = 0; nf < 8; ++nf) {
            const int col = n0 + 8 * nf + 2 * q4;
            const float bA = s_b1[col], bBv = s_b1[col + 1];
            const int r0 = m0 + 16 * mt + g, r1 = r0 + 8;
            *(uint32_t*)(dsm + A_OFF + toff(r0, col)) =
                cvt_h2(fmaxf(acc[mt][nf][0] + bA, 0.0f),
                       fmaxf(acc[mt][nf][1] + bBv, 0.0f));
            *(uint32_t*)(dsm + A_OFF + toff(r1, col)) =
                cvt_h2(fmaxf(acc[mt][nf][2] + bA, 0.0f),
                       fmaxf(acc[mt][nf][3] + bBv, 0.0f));
        }
    }
    __syncthreads();

    // ---- actor phase 2: logits = hh@w2h + hh@w2l (A fragment shared) ----
    {
        const int arow = wid * 16 + lane15;
        const uint32_t aoff = arow * 256;
        const int r7 = arow & 7;
        const uint32_t boffp = lane15 * 256;
        const int r7p = lane15 & 7;
        const uint32_t w2hA = smem_u32(s_w2h), w2lA = smem_u32(s_w2l);

        float ac2[2][4];
        #pragma unroll
        for (int i = 0; i < 2; ++i)
            #pragma unroll
            for (int c = 0; c < 4; ++c) ac2[i][c] = 0.0f;

        #pragma unroll
        for (int ks = 0; ks < 8; ++ks) {
            const int c0 = 2 * ks + laneh;
            uint32_t af[4], bh[4], bl[4];
            ldsm4(af, db + A_OFF + aoff + (uint32_t)((c0 ^ r7) << 4));
            const uint32_t co = (uint32_t)((c0 ^ r7p) << 4);
            ldsm4(bh, w2hA + boffp + co);
            ldsm4(bl, w2lA + boffp + co);
            mma16816(ac2[0], af, bh[0], bh[2]);
            mma16816(ac2[1], af, bh[1], bh[3]);
            mma16816(ac2[0], af, bl[0], bl[2]);
            mma16816(ac2[1], af, bl[1], bl[3]);
        }

        const int r0 = wid * 16 + g, r1 = r0 + 8;
        const int tok0 = s_idx[r0], tok1 = s_idx[r1];
        #pragma unroll
        for (int nf = 0; nf < 2; ++nf) {
            const int cl = 8 * nf + 2 * q4;
            const float bA = s_b2[cl], bBv = s_b2[cl + 1];
            if (tok0 >= 0) {
                float2 v = {ac2[nf][0] + bA, ac2[nf][1] + bBv};
                *(float2*)(out + (size_t)tok0 * NACT + cl) = v;
            }
            if (tok1 >= 0) {
                float2 v = {ac2[nf][2] + bA, ac2[nf][3] + bBv};
                *(float2*)(out + (size_t)tok1 * NACT + cl) = v;
            }
        }
    }
}

// ---------------- launch ----------------
extern "C" void kernel_launch(void* const* d_in, const int* in_sizes, int n_in,
                              void* d_out, int out_size) {
    const float* obs   = (const float*)d_in[0];
    const int*   pick  = (const int*)  d_in[1];
    const int*   htype = (const int*)  d_in[2];
    const int*   gsel  = (const int*)  d_in[3];
    const float* W1    = (const float*)d_in[4];
    const float* b1    = (const float*)d_in[5];
    const float* W2    = (const float*)d_in[6];
    const float* b2    = (const float*)d_in[7];
    const float* Wc1   = (const float*)d_in[8];
    const float* bc1   = (const float*)d_in[9];
    const float* Wc2   = (const float*)d_in[10];
    const float* bc2   = (const float*)d_in[11];
    float* out = (float*)d_out;

    cudaFuncSetAttribute(k_main, cudaFuncAttributeMaxDynamicSharedMemorySize, DYN_SMEM);

    k_init        <<<1, 32>>>();
    k_histscan    <<<512, 256>>>(pick);
    k_scatter_prep<<<512 + NEXP + 1, 256>>>(pick, W1, W2, Wc1);
    k_main        <<<2 * NTILES, 256, DYN_SMEM>>>(obs, htype, gsel,
                                                  b1, b2, bc1, bc2, Wc2, out);
}